// round 4
// baseline (speedup 1.0000x reference)
#include <cuda_runtime.h>
#include <cuda_bf16.h>
#include <cstdint>
#include <cstddef>

#define LATENT   2000
#define NG       10000
#define KER      20
#define BATCH    128
#define NTILE    80          // groups per CTA; 10000 = 125*80
#define NCTA     125
#define KT       32          // K per tile
#define NTIL     63          // ceil(2000/32), last tile half-full (zero padded)
#define STG      3           // smem ring stages
#define ROWS     208         // 128 A rows + 80 B rows
#define PITCHB   80          // bytes per staged row: 32 bf16 = 64B + 16B pad (conflict-free LDS)
#define STG_BYTES (ROWS*PITCHB)          // 16640

#define OFF_STG  0
#define OFF_HS   (STG*STG_BYTES)         // 49920 ; h_s: 128*80 f32
#define OFF_RS   (OFF_HS + 40960)        // red_s 8*80 f32
#define OFF_RQ   (OFF_RS + 2560)         // red_q
#define OFF_SSC  (OFF_RQ + 2560)
#define OFF_SSH  (OFF_SSC + 320)
#define OFF_SCW  (OFF_SSH + 320)         // conv_w 80*20 f32
#define OFF_SCB  (OFF_SCW + 6400)
#define SMEM_BYTES (OFF_SCB + 320)       // 103680 total

__device__ __forceinline__ uint32_t packbf(float lo, float hi) {
    uint32_t r;
    asm("cvt.rn.bf16x2.f32 %0, %1, %2;" : "=r"(r) : "f"(hi), "f"(lo));
    return r;
}
__device__ __forceinline__ float sigf(float y) {
    return __fdividef(1.f, 1.f + __expf(-y));
}

__global__ void __launch_bounds__(512, 1)
fused_decoder(const float* __restrict__ z,
              const float* __restrict__ Wfc,
              const float* __restrict__ gamma,
              const float* __restrict__ beta,
              const float* __restrict__ convw,
              const float* __restrict__ convb,
              float* __restrict__ out)
{
    extern __shared__ char smem[];
    float* h_s    = (float*)(smem + OFF_HS);
    float* red_s  = (float*)(smem + OFF_RS);
    float* red_q  = (float*)(smem + OFF_RQ);
    float* sscale = (float*)(smem + OFF_SSC);
    float* sshift = (float*)(smem + OFF_SSH);
    float* scw    = (float*)(smem + OFF_SCW);
    float* scb    = (float*)(smem + OFF_SCB);

    const int tid  = threadIdx.x;
    const int w    = tid >> 5;
    const int lane = tid & 31;
    const int kq   = lane & 3;           // t%4
    const int rq   = lane >> 2;          // t/4
    const int mstrip = (w & 7) << 4;     // 8 m-strips of 16
    const int nbase  = (w >> 3) * 40;    // 2 n-halves of 40
    const int g0     = blockIdx.x * NTILE;

    // conv params
    for (int i = tid; i < NTILE * KER; i += 512)
        scw[i] = convw[(size_t)g0 * KER + i];
    if (tid < NTILE) scb[tid] = convb[g0 + tid];

    // ---- producer chunk precompute: 1664 float4-chunks (A:1024, B:640) ----
    // chunk c: row8 = c>>3 (0..207), col8 = c&7; k0(t) = t*32 + col8*4
    const int nch = (tid < 128) ? 4 : 3;
    const float* srcp[4];
    int stoff[4], kbase[4];
    #pragma unroll
    for (int i = 0; i < 4; ++i) {
        const int c = tid + i * 512;
        const int cc = (c < 1664) ? c : 0;
        const int row8 = cc >> 3;
        const int col8 = cc & 7;
        srcp[i]  = (row8 < 128) ? z + (size_t)row8 * LATENT + col8 * 4
                                : Wfc + (size_t)(g0 + row8 - 128) * LATENT + col8 * 4;
        stoff[i] = row8 * PITCHB + col8 * 8;
        kbase[i] = col8 * 4;
    }

    float4 fifo[2][4];
    auto ldg_tile = [&](int t, int slot) {
        #pragma unroll
        for (int i = 0; i < 4; ++i) {
            if (i >= nch) break;
            const bool v = (t * KT + kbase[i]) < LATENT;
            fifo[slot][i] = v ? *(const float4*)(srcp[i] + t * KT)
                              : make_float4(0.f, 0.f, 0.f, 0.f);
        }
    };
    auto cvt_sts = [&](int slot, int s) {
        char* base = smem + OFF_STG + s * STG_BYTES;
        #pragma unroll
        for (int i = 0; i < 4; ++i) {
            if (i >= nch) break;
            const float4 f = fifo[slot][i];
            uint2 u;
            u.x = packbf(f.x, f.y);
            u.y = packbf(f.z, f.w);
            *(uint2*)(base + stoff[i]) = u;
        }
    };

    float d[5][4];
    #pragma unroll
    for (int i = 0; i < 5; ++i)
        #pragma unroll
        for (int j = 0; j < 4; ++j) d[i][j] = 0.f;

    // ---- prologue ----
    ldg_tile(0, 0);
    ldg_tile(1, 1);
    cvt_sts(0, 0);
    __syncthreads();

    // ---- main loop ----
    #pragma unroll 1
    for (int t = 0; t < NTIL; ++t) {
        const int s = t % 3;
        if (t + 2 < NTIL) ldg_tile(t + 2, t & 1);
        if (t + 1 < NTIL) cvt_sts((t + 1) & 1, (t + 1) % 3);

        const char* zb = smem + OFF_STG + s * STG_BYTES;
        const char* wb = zb + 128 * PITCHB;
        #pragma unroll
        for (int ks = 0; ks < 2; ++ks) {
            const int kb = ks * 32 + kq * 4;     // byte offset of bf16x2 in row
            const uint32_t a0 = *(const uint32_t*)(zb + (mstrip + rq)     * PITCHB + kb);
            const uint32_t a1 = *(const uint32_t*)(zb + (mstrip + rq + 8) * PITCHB + kb);
            const uint32_t a2 = *(const uint32_t*)(zb + (mstrip + rq)     * PITCHB + kb + 16);
            const uint32_t a3 = *(const uint32_t*)(zb + (mstrip + rq + 8) * PITCHB + kb + 16);
            #pragma unroll
            for (int nt = 0; nt < 5; ++nt) {
                const char* brow = wb + (nbase + nt * 8 + rq) * PITCHB + kb;
                const uint32_t b0 = *(const uint32_t*)(brow);
                const uint32_t b1 = *(const uint32_t*)(brow + 16);
                asm volatile(
                    "mma.sync.aligned.m16n8k16.row.col.f32.bf16.bf16.f32 "
                    "{%0,%1,%2,%3}, {%4,%5,%6,%7}, {%8,%9}, {%0,%1,%2,%3};\n"
                    : "+f"(d[nt][0]), "+f"(d[nt][1]), "+f"(d[nt][2]), "+f"(d[nt][3])
                    : "r"(a0), "r"(a1), "r"(a2), "r"(a3), "r"(b0), "r"(b1));
            }
        }
        __syncthreads();
    }

    // ---- BatchNorm stats (b_fc cancels under mean subtraction) ----
    #pragma unroll
    for (int nt = 0; nt < 5; ++nt) {
        float s0 = d[nt][0] + d[nt][2];
        float s1 = d[nt][1] + d[nt][3];
        float q0 = d[nt][0] * d[nt][0] + d[nt][2] * d[nt][2];
        float q1 = d[nt][1] * d[nt][1] + d[nt][3] * d[nt][3];
        #pragma unroll
        for (int o = 4; o < 32; o <<= 1) {
            s0 += __shfl_xor_sync(0xffffffffu, s0, o);
            s1 += __shfl_xor_sync(0xffffffffu, s1, o);
            q0 += __shfl_xor_sync(0xffffffffu, q0, o);
            q1 += __shfl_xor_sync(0xffffffffu, q1, o);
        }
        if (rq == 0) {
            const int n = nbase + nt * 8 + kq * 2;
            red_s[(w & 7) * 80 + n]     = s0;
            red_s[(w & 7) * 80 + n + 1] = s1;
            red_q[(w & 7) * 80 + n]     = q0;
            red_q[(w & 7) * 80 + n + 1] = q1;
        }
    }
    __syncthreads();
    if (tid < NTILE) {
        float s = 0.f, q = 0.f;
        #pragma unroll
        for (int i = 0; i < 8; ++i) { s += red_s[i * 80 + tid]; q += red_q[i * 80 + tid]; }
        const float mean = s * (1.f / BATCH);
        const float var  = q * (1.f / BATCH) - mean * mean;
        const float scv  = gamma[g0 + tid] * rsqrtf(var + 1e-5f);
        sscale[tid] = scv;
        sshift[tid] = beta[g0 + tid] - mean * scv;
    }
    __syncthreads();

    // ---- normalize + LeakyReLU -> h_s ----
    #pragma unroll
    for (int nt = 0; nt < 5; ++nt) {
        #pragma unroll
        for (int c = 0; c < 4; ++c) {
            const int n = nbase + nt * 8 + kq * 2 + (c & 1);
            const int m = mstrip + rq + ((c >> 1) << 3);
            float hn = d[nt][c] * sscale[n] + sshift[n];
            hn = fmaxf(hn, 0.1f * hn);
            h_s[m * 80 + n] = hn;
        }
    }
    __syncthreads();

    // ---- epilogue: conv outer product + LeakyReLU + sigmoid, coalesced float4 stores ----
    const size_t outb = (size_t)g0 * KER;
    for (int i = tid; i < 128 * 400; i += 512) {
        const int m = i / 400;
        const int j = (i - m * 400) * 4;     // 0..1596 step 4; 20 % 4 == 0
        const int n = j / 20;
        const int k = j - n * 20;
        const float hn = h_s[m * 80 + n];
        const float cb = scb[n];
        const float4 wv = *(const float4*)&scw[n * KER + k];
        float4 y;
        float t0 = hn * wv.x + cb; t0 = fmaxf(t0, 0.1f * t0); y.x = sigf(t0);
        float t1 = hn * wv.y + cb; t1 = fmaxf(t1, 0.1f * t1); y.y = sigf(t1);
        float t2 = hn * wv.z + cb; t2 = fmaxf(t2, 0.1f * t2); y.z = sigf(t2);
        float t3 = hn * wv.w + cb; t3 = fmaxf(t3, 0.1f * t3); y.w = sigf(t3);
        *(float4*)(out + (size_t)m * ((size_t)NG * KER) + outb + j) = y;
    }
}

extern "C" void kernel_launch(void* const* d_in, const int* in_sizes, int n_in,
                              void* d_out, int out_size) {
    const float* z     = (const float*)d_in[0];
    const float* Wfc   = (const float*)d_in[1];
    // d_in[2] = b_fc: cancelled analytically by BN mean subtraction
    const float* gamma = (const float*)d_in[3];
    const float* beta  = (const float*)d_in[4];
    const float* convw = (const float*)d_in[5];
    const float* convb = (const float*)d_in[6];
    cudaFuncSetAttribute(fused_decoder, cudaFuncAttributeMaxDynamicSharedMemorySize, SMEM_BYTES);
    fused_decoder<<<NCTA, 512, SMEM_BYTES>>>(z, Wfc, gamma, beta, convw, convb, (float*)d_out);
}

// round 5
// speedup vs baseline: 1.6345x; 1.6345x over previous
#include <cuda_runtime.h>
#include <cuda_bf16.h>
#include <cstdint>
#include <cstddef>

#define LATENT   2000
#define NG       10000
#define KER      20
#define BATCH    128
#define NTILE    80          // groups per CTA; 10000 = 125*80
#define NCTA     125
#define KT       32          // K per tile
#define NTIL     63          // ceil(2000/32), last tile half (zero padded)
#define ROWS     208         // 128 A rows + 80 B rows
#define PITCHB   80          // bytes/staged row: 32 bf16 = 64B + 16B pad (conflict-free)
#define STG_BYTES (ROWS*PITCHB)          // 16640

#define OFF_STG  0
#define OFF_HS   (3*STG_BYTES)           // 49920 ; h_s: 128*80 f32
#define OFF_RS   (OFF_HS + 40960)        // red_s 8*80 f32
#define OFF_RQ   (OFF_RS + 2560)         // red_q
#define OFF_SSC  (OFF_RQ + 2560)
#define OFF_SSH  (OFF_SSC + 320)
#define OFF_SCW  (OFF_SSH + 320)         // conv_w 80*20 f32
#define OFF_SCB  (OFF_SCW + 6400)
#define SMEM_BYTES (OFF_SCB + 320)       // 103680

__device__ __forceinline__ uint32_t packbf(float lo, float hi) {
    uint32_t r;
    asm("cvt.rn.bf16x2.f32 %0, %1, %2;" : "=r"(r) : "f"(hi), "f"(lo));
    return r;
}
__device__ __forceinline__ float sigf(float y) {
    return __fdividef(1.f, 1.f + __expf(-y));
}

__global__ void __launch_bounds__(512, 1)
fused_decoder(const float* __restrict__ z,
              const float* __restrict__ Wfc,
              const float* __restrict__ gamma,
              const float* __restrict__ beta,
              const float* __restrict__ convw,
              const float* __restrict__ convb,
              float* __restrict__ out)
{
    extern __shared__ char smem[];
    float* h_s    = (float*)(smem + OFF_HS);
    float* red_s  = (float*)(smem + OFF_RS);
    float* red_q  = (float*)(smem + OFF_RQ);
    float* sscale = (float*)(smem + OFF_SSC);
    float* sshift = (float*)(smem + OFF_SSH);
    float* scw    = (float*)(smem + OFF_SCW);
    float* scb    = (float*)(smem + OFF_SCB);

    const int tid  = threadIdx.x;
    const int w    = tid >> 5;
    const int lane = tid & 31;
    const int kq   = lane & 3;
    const int rq   = lane >> 2;
    const int mstrip = (w & 7) << 4;     // 8 m-strips of 16
    const int nbase  = (w >> 3) * 40;    // 2 n-halves of 40
    const int g0     = blockIdx.x * NTILE;

    for (int i = tid; i < NTILE * KER; i += 512)
        scw[i] = convw[(size_t)g0 * KER + i];
    if (tid < NTILE) scb[tid] = convb[g0 + tid];

    // ---- producer chunks: 1664 float4-chunks (A:1024, B:640) ----
    const int nch = (tid < 128) ? 4 : 3;
    const float* srcp[4];
    int stoff[4], kbase[4];
    #pragma unroll
    for (int i = 0; i < 4; ++i) {
        const int c = tid + i * 512;
        const int cc = (c < 1664) ? c : 0;
        const int row8 = cc >> 3;
        const int col8 = cc & 7;
        srcp[i]  = (row8 < 128) ? z + (size_t)row8 * LATENT + col8 * 4
                                : Wfc + (size_t)(g0 + row8 - 128) * LATENT + col8 * 4;
        stoff[i] = row8 * PITCHB + col8 * 8;
        kbase[i] = col8 * 4;
    }

    float4 fifo[3][4];   // 3-tile-deep register FIFO
    auto ldg_tile = [&](int t, int slot) {
        #pragma unroll
        for (int i = 0; i < 4; ++i) {
            if (i >= nch) break;
            const bool v = (t * KT + kbase[i]) < LATENT;
            fifo[slot][i] = v ? *(const float4*)(srcp[i] + t * KT)
                              : make_float4(0.f, 0.f, 0.f, 0.f);
        }
    };
    auto cvt_sts = [&](int slot, int s) {
        char* base = smem + OFF_STG + s * STG_BYTES;
        #pragma unroll
        for (int i = 0; i < 4; ++i) {
            if (i >= nch) break;
            const float4 f = fifo[slot][i];
            uint2 u;
            u.x = packbf(f.x, f.y);
            u.y = packbf(f.z, f.w);
            *(uint2*)(base + stoff[i]) = u;
        }
    };

    float d[5][4];
    #pragma unroll
    for (int i = 0; i < 5; ++i)
        #pragma unroll
        for (int j = 0; j < 4; ++j) d[i][j] = 0.f;

    auto mma_stage = [&](int s) {
        const char* zb = smem + OFF_STG + s * STG_BYTES;
        const char* wb = zb + 128 * PITCHB;
        #pragma unroll
        for (int ks = 0; ks < 2; ++ks) {
            const int kb = ks * 32 + kq * 4;
            const uint32_t a0 = *(const uint32_t*)(zb + (mstrip + rq)     * PITCHB + kb);
            const uint32_t a1 = *(const uint32_t*)(zb + (mstrip + rq + 8) * PITCHB + kb);
            const uint32_t a2 = *(const uint32_t*)(zb + (mstrip + rq)     * PITCHB + kb + 16);
            const uint32_t a3 = *(const uint32_t*)(zb + (mstrip + rq + 8) * PITCHB + kb + 16);
            #pragma unroll
            for (int nt = 0; nt < 5; ++nt) {
                const char* brow = wb + (nbase + nt * 8 + rq) * PITCHB + kb;
                const uint32_t b0 = *(const uint32_t*)(brow);
                const uint32_t b1 = *(const uint32_t*)(brow + 16);
                asm volatile(
                    "mma.sync.aligned.m16n8k16.row.col.f32.bf16.bf16.f32 "
                    "{%0,%1,%2,%3}, {%4,%5,%6,%7}, {%8,%9}, {%0,%1,%2,%3};\n"
                    : "+f"(d[nt][0]), "+f"(d[nt][1]), "+f"(d[nt][2]), "+f"(d[nt][3])
                    : "r"(a0), "r"(a1), "r"(a2), "r"(a3), "r"(b0), "r"(b1));
            }
        }
    };

    // ---- prologue: 3 tiles of LDG in flight ----
    ldg_tile(0, 0);
    ldg_tile(1, 1);
    ldg_tile(2, 2);
    cvt_sts(0, 0);
    __syncthreads();

    // ---- main loop: 21 blocks of 3 tiles, all indices static ----
    #pragma unroll 1
    for (int tb = 0; tb < 21; ++tb) {
        const int t0 = tb * 3;
        #pragma unroll
        for (int ti = 0; ti < 3; ++ti) {
            const int t = t0 + ti;
            if (t + 3 < NTIL) ldg_tile(t + 3, ti);              // fifo slot (t+3)%3 == ti
            if (t + 1 < NTIL) cvt_sts((ti + 1) % 3, (ti + 1) % 3); // tile t+1 -> stage (t+1)%3
            mma_stage(ti);                                       // stage t%3 == ti
            __syncthreads();
        }
    }

    // ---- BatchNorm stats (b_fc cancels under mean subtraction) ----
    #pragma unroll
    for (int nt = 0; nt < 5; ++nt) {
        float s0 = d[nt][0] + d[nt][2];
        float s1 = d[nt][1] + d[nt][3];
        float q0 = d[nt][0] * d[nt][0] + d[nt][2] * d[nt][2];
        float q1 = d[nt][1] * d[nt][1] + d[nt][3] * d[nt][3];
        #pragma unroll
        for (int o = 4; o < 32; o <<= 1) {
            s0 += __shfl_xor_sync(0xffffffffu, s0, o);
            s1 += __shfl_xor_sync(0xffffffffu, s1, o);
            q0 += __shfl_xor_sync(0xffffffffu, q0, o);
            q1 += __shfl_xor_sync(0xffffffffu, q1, o);
        }
        if (rq == 0) {
            const int n = nbase + nt * 8 + kq * 2;
            red_s[(w & 7) * 80 + n]     = s0;
            red_s[(w & 7) * 80 + n + 1] = s1;
            red_q[(w & 7) * 80 + n]     = q0;
            red_q[(w & 7) * 80 + n + 1] = q1;
        }
    }
    __syncthreads();
    if (tid < NTILE) {
        float s = 0.f, q = 0.f;
        #pragma unroll
        for (int i = 0; i < 8; ++i) { s += red_s[i * 80 + tid]; q += red_q[i * 80 + tid]; }
        const float mean = s * (1.f / BATCH);
        const float var  = q * (1.f / BATCH) - mean * mean;
        const float scv  = gamma[g0 + tid] * rsqrtf(var + 1e-5f);
        sscale[tid] = scv;
        sshift[tid] = beta[g0 + tid] - mean * scv;
    }
    __syncthreads();

    // ---- normalize + LeakyReLU -> h_s ----
    #pragma unroll
    for (int nt = 0; nt < 5; ++nt) {
        #pragma unroll
        for (int c = 0; c < 4; ++c) {
            const int n = nbase + nt * 8 + kq * 2 + (c & 1);
            const int m = mstrip + rq + ((c >> 1) << 3);
            float hn = d[nt][c] * sscale[n] + sshift[n];
            hn = fmaxf(hn, 0.1f * hn);
            h_s[m * 80 + n] = hn;
        }
    }
    __syncthreads();

    // ---- epilogue: conv outer product + LeakyReLU + sigmoid, coalesced ----
    const size_t outb = (size_t)g0 * KER;
    for (int i = tid; i < 128 * 400; i += 512) {
        const int m = i / 400;
        const int j = (i - m * 400) * 4;     // 20 % 4 == 0 -> n,k well defined
        const int n = j / 20;
        const int k = j - n * 20;
        const float hn = h_s[m * 80 + n];
        const float cb = scb[n];
        const float4 wv = *(const float4*)&scw[n * KER + k];
        float4 y;
        float t0 = hn * wv.x + cb; t0 = fmaxf(t0, 0.1f * t0); y.x = sigf(t0);
        float t1 = hn * wv.y + cb; t1 = fmaxf(t1, 0.1f * t1); y.y = sigf(t1);
        float t2 = hn * wv.z + cb; t2 = fmaxf(t2, 0.1f * t2); y.z = sigf(t2);
        float t3 = hn * wv.w + cb; t3 = fmaxf(t3, 0.1f * t3); y.w = sigf(t3);
        *(float4*)(out + (size_t)m * ((size_t)NG * KER) + outb + j) = y;
    }
}

extern "C" void kernel_launch(void* const* d_in, const int* in_sizes, int n_in,
                              void* d_out, int out_size) {
    const float* z     = (const float*)d_in[0];
    const float* Wfc   = (const float*)d_in[1];
    // d_in[2] = b_fc: cancelled analytically by BN mean subtraction
    const float* gamma = (const float*)d_in[3];
    const float* beta  = (const float*)d_in[4];
    const float* convw = (const float*)d_in[5];
    const float* convb = (const float*)d_in[6];
    cudaFuncSetAttribute(fused_decoder, cudaFuncAttributeMaxDynamicSharedMemorySize, SMEM_BYTES);
    fused_decoder<<<NCTA, 512, SMEM_BYTES>>>(z, Wfc, gamma, beta, convw, convb, (float*)d_out);
}